// round 15
// baseline (speedup 1.0000x reference)
#include <cuda_runtime.h>
#include <cuda_bf16.h>
#include <math.h>

#define NN 50000
#define EE 800000
#define HH 128
#define FIN 64
#define CC 16
#define LL 3

// ---------------- scratch (static device globals; no allocation) ----------------
__device__ float g_h[NN * HH];            // hidden state  [N,128]
__device__ __nv_bfloat162 g_m2[NN * 64];  // messages, bf16 pairs [N,128]
__device__ float g_agg[NN * HH];          // aggregated    [N,128]
__device__ unsigned g_Wtp[LL * HH * HH];  // W^T per layer, tf32 fragment-permuted
__device__ unsigned g_Wihp[3 * HH * HH];  // w_ih tf32 fragment-permuted
__device__ unsigned g_Whhp[3 * HH * HH];  // w_hh tf32 fragment-permuted
__device__ int   g_edge[2 * EE];
__device__ int   g_deg[NN];
__device__ int   g_rowptr[NN + 1];
__device__ int   g_cursor[NN];
__device__ int   g_col[EE];
__device__ int   g_bsum[256];
__device__ int   g_boff[256];
__device__ int   g_is64;

// ---------------- side stream + events (created at static init, before any
// harness memory checkpoint; no device-memory allocation in kernel_launch) ----
static cudaStream_t s_side;
static cudaEvent_t s_fork, s_join;
namespace {
struct _StreamInit {
    _StreamInit() {
        cudaStreamCreateWithFlags(&s_side, cudaStreamNonBlocking);
        cudaEventCreateWithFlags(&s_fork, cudaEventDisableTiming);
        cudaEventCreateWithFlags(&s_join, cudaEventDisableTiming);
    }
};
_StreamInit _stream_init;
}

// ---------------- edge dtype probe ----------------
__global__ void k_detect(const void* ei) {
    if (blockIdx.x == 0 && threadIdx.x == 0) {
        const long long* p64 = (const long long*)ei;
        int ok64 = 1;
        for (int i = 0; i < 64; ++i) {
            long long v = p64[i];
            if (v < 0 || v >= NN) { ok64 = 0; break; }
        }
        g_is64 = ok64;
    }
}

// convert + histogram fused (g_deg must be zeroed first)
__global__ void k_convhist(const void* ei) {
    int e = blockIdx.x * blockDim.x + threadIdx.x;
    if (e < 2 * EE) {
        int v;
        if (g_is64) v = (int)((const long long*)ei)[e];
        else        v = ((const int*)ei)[e];
        g_edge[e] = v;
        if (e >= EE) atomicAdd(&g_deg[v], 1);   // dst half
    }
}

// ---------------- init ----------------
__global__ void k_pad(const float* __restrict__ x) {
    int i = blockIdx.x * blockDim.x + threadIdx.x;
    if (i < NN * HH) {
        int n = i >> 7, k = i & 127;
        g_h[i] = (k < FIN) ? x[n * FIN + k] : 0.f;
    }
}

__device__ __forceinline__ unsigned f2tf(float x) {
    unsigned r;
    asm("cvt.rna.tf32.f32 %0, %1;" : "=r"(r) : "f"(x));
    return r;
}

// Fragment-permuted B layout for mma.m16n8k8 tf32 B operand (full K=128)
__device__ __forceinline__ int bperm_off(int n, int k) {
    int g = n >> 7, nf = (n >> 3) & 15, nl = n & 7;
    int ks = k >> 3, hi = (k & 7) >> 2, c = k & 3;
    return ((g * 16 + nf) * 16 + ks) * 64 + (nl * 4 + c) * 2 + hi;
}

// pre-round + pre-permute all GEMM B operands once
__global__ void k_prep(const float* __restrict__ W,
                       const float* __restrict__ w_ih,
                       const float* __restrict__ w_hh) {
    int i = blockIdx.x * blockDim.x + threadIdx.x;   // 65536 threads
    if (i < LL * HH * HH) {
        int l = i >> 14;
        int rem = i & 16383;
        int n = rem >> 7, k = rem & 127;             // Bt[n][k] = W[l][k][n]
        g_Wtp[(l << 14) + bperm_off(n, k)] = f2tf(W[(l << 14) + k * 128 + n]);
    }
    if (i < 3 * HH * HH) {
        int n = i >> 7, k = i & 127;
        int off = bperm_off(n, k);
        g_Wihp[off] = f2tf(w_ih[i]);
        g_Whhp[off] = f2tf(w_hh[i]);
    }
}

// ---------------- CSR build ----------------
__global__ void k_zero_deg() {
    int i = blockIdx.x * blockDim.x + threadIdx.x;
    if (i < NN) g_deg[i] = 0;
}

__global__ void k_scan1() {
    __shared__ int s[256];
    int t = threadIdx.x;
    int idx = blockIdx.x * 256 + t;
    int v = (idx < NN) ? g_deg[idx] : 0;
    s[t] = v;
    __syncthreads();
#pragma unroll
    for (int off = 1; off < 256; off <<= 1) {
        int add = (t >= off) ? s[t - off] : 0;
        __syncthreads();
        s[t] += add;
        __syncthreads();
    }
    if (idx < NN) g_rowptr[idx] = s[t] - v;
    if (t == 255) g_bsum[blockIdx.x] = s[255];
}

__global__ void k_scan2(int nblocks) {
    __shared__ int s[256];
    int t = threadIdx.x;
    int v = (t < nblocks) ? g_bsum[t] : 0;
    s[t] = v;
    __syncthreads();
#pragma unroll
    for (int off = 1; off < 256; off <<= 1) {
        int add = (t >= off) ? s[t - off] : 0;
        __syncthreads();
        s[t] += add;
        __syncthreads();
    }
    if (t < nblocks) g_boff[t] = s[t] - v;
}

__global__ void k_scan3() {
    int idx = blockIdx.x * 256 + threadIdx.x;
    if (idx < NN) {
        int v = g_rowptr[idx] + g_boff[blockIdx.x];
        g_rowptr[idx] = v;
        g_cursor[idx] = v;
    }
    if (idx == 0) g_rowptr[NN] = EE;
}

__global__ void k_fill() {
    int e = blockIdx.x * blockDim.x + threadIdx.x;
    if (e < EE) {
        int d = g_edge[EE + e];
        int srcn = g_edge[e];
        int pos = atomicAdd(&g_cursor[d], 1);
        g_col[pos] = srcn;
    }
}

// ---------------- aggregation: warp per node, bf16 m rows ----------------
__global__ void k_gather() {
    int warp = (blockIdx.x * blockDim.x + threadIdx.x) >> 5;
    int lane = threadIdx.x & 31;
    if (warp >= NN) return;
    int beg = g_rowptr[warp], end = g_rowptr[warp + 1];
    float a0 = 0.f, a1 = 0.f, a2 = 0.f, a3 = 0.f;
    int e = beg;
    for (; e + 2 <= end; e += 2) {
        int s0 = g_col[e], s1 = g_col[e + 1];
        uint2 v0 = *(const uint2*)&g_m2[s0 * 64 + lane * 2];
        uint2 v1 = *(const uint2*)&g_m2[s1 * 64 + lane * 2];
        float2 p0 = __bfloat1622float2(*(__nv_bfloat162*)&v0.x);
        float2 p1 = __bfloat1622float2(*(__nv_bfloat162*)&v0.y);
        float2 q0 = __bfloat1622float2(*(__nv_bfloat162*)&v1.x);
        float2 q1 = __bfloat1622float2(*(__nv_bfloat162*)&v1.y);
        a0 += p0.x + q0.x;
        a1 += p0.y + q0.y;
        a2 += p1.x + q1.x;
        a3 += p1.y + q1.y;
    }
    if (e < end) {
        uint2 v0 = *(const uint2*)&g_m2[g_col[e] * 64 + lane * 2];
        float2 p0 = __bfloat1622float2(*(__nv_bfloat162*)&v0.x);
        float2 p1 = __bfloat1622float2(*(__nv_bfloat162*)&v0.y);
        a0 += p0.x; a1 += p0.y; a2 += p1.x; a3 += p1.y;
    }
    *(float4*)&g_agg[warp * HH + lane * 4] = make_float4(a0, a1, a2, a3);
}

// ---------------- shared GEMM machinery (M-tile 64, full K=128) ----------------
__device__ __forceinline__ void stageA64(unsigned* As, const float* __restrict__ A,
                                         int row0, int t) {
#pragma unroll
    for (int q = 0; q < 8; ++q) {
        int idx = q * 256 + t;
        int m = idx >> 5, kq = idx & 31;
        int row = row0 + m;
        float4 v = make_float4(0.f, 0.f, 0.f, 0.f);
        if (row < NN) v = *(const float4*)&A[row * 128 + kq * 4];
        int mf = m >> 4, r16 = m & 15;
        int lb = (r16 & 7) * 4, rh = r16 >> 3;
        int ks = kq >> 1, hi = kq & 1, reg = hi * 2 + rh;
        unsigned* dst = &As[(mf * 16 + ks) * 128];
        dst[(lb + 0) * 4 + reg] = f2tf(v.x);
        dst[(lb + 1) * 4 + reg] = f2tf(v.y);
        dst[(lb + 2) * 4 + reg] = f2tf(v.z);
        dst[(lb + 3) * 4 + reg] = f2tf(v.w);
    }
}

// staged A-slot for a single (m, k) element
__device__ __forceinline__ int aslot(int m, int k) {
    return ((m >> 4) * 16 + (k >> 3)) * 128 + ((m & 7) * 4 + (k & 3)) * 4 +
           ((k >> 2) & 1) * 2 + ((m >> 3) & 1);
}

// accumulate one 64x128xK group GEMM into c (no zero-init); KS = k-steps (8 per 64 k)
template <int KS>
__device__ __forceinline__ void mmaAccT(const unsigned* As, const unsigned* __restrict__ Bg,
                                        float c[2][4][4], int wm, int wn, int lane) {
#pragma unroll
    for (int ks = 0; ks < KS; ++ks) {
        uint2 b[4];
#pragma unroll
        for (int j = 0; j < 4; ++j)
            b[j] = *(const uint2*)&Bg[((wn * 4 + j) * 16 + ks) * 64 + lane * 2];
        uint4 a[2];
#pragma unroll
        for (int i = 0; i < 2; ++i)
            a[i] = *(const uint4*)&As[((wm * 2 + i) * 16 + ks) * 128 + lane * 4];
#pragma unroll
        for (int i = 0; i < 2; ++i)
#pragma unroll
            for (int j = 0; j < 4; ++j) {
                asm volatile(
                    "mma.sync.aligned.m16n8k8.row.col.f32.tf32.tf32.f32 "
                    "{%0,%1,%2,%3}, {%4,%5,%6,%7}, {%8,%9}, {%0,%1,%2,%3};"
                    : "+f"(c[i][j][0]), "+f"(c[i][j][1]),
                      "+f"(c[i][j][2]), "+f"(c[i][j][3])
                    : "r"(a[i].x), "r"(a[i].y), "r"(a[i].z), "r"(a[i].w),
                      "r"(b[j].x), "r"(b[j].y));
            }
    }
}
#define mmaAcc mmaAccT<16>

__device__ __forceinline__ void zeroC(float c[2][4][4]) {
#pragma unroll
    for (int i = 0; i < 2; ++i)
#pragma unroll
        for (int j = 0; j < 4; ++j)
#pragma unroll
            for (int r = 0; r < 4; ++r) c[i][j][r] = 0.f;
}

// ---------------- layer-0 m GEMM: reads x directly, K=64 ----------------
__global__ __launch_bounds__(256, 2) void k_mma0(const float* __restrict__ x,
                                                 const unsigned* __restrict__ Bp) {
    __shared__ unsigned As[8192];
    int t = threadIdx.x, lane = t & 31, w = t >> 5;
    int wm = w >> 2, wn = w & 3;
    int row0 = blockIdx.x * 64;
    // stage x tile: 64 rows x 64 cols (k-steps 0..7 of the fragment layout)
#pragma unroll
    for (int q = 0; q < 4; ++q) {
        int idx = q * 256 + t;
        int m = idx >> 4, kq = idx & 15;        // kq: quad of 4 within 64 cols
        int row = row0 + m;
        float4 v = make_float4(0.f, 0.f, 0.f, 0.f);
        if (row < NN) v = *(const float4*)&x[row * FIN + kq * 4];
        int mf = m >> 4, r16 = m & 15;
        int lb = (r16 & 7) * 4, rh = r16 >> 3;
        int ks = kq >> 1, hi = kq & 1, reg = hi * 2 + rh;
        unsigned* dst = &As[(mf * 16 + ks) * 128];
        dst[(lb + 0) * 4 + reg] = f2tf(v.x);
        dst[(lb + 1) * 4 + reg] = f2tf(v.y);
        dst[(lb + 2) * 4 + reg] = f2tf(v.z);
        dst[(lb + 3) * 4 + reg] = f2tf(v.w);
    }
    __syncthreads();
    float c[2][4][4];
    zeroC(c);
    mmaAccT<8>(As, Bp, c, wm, wn, lane);       // only K=64 (h cols 64..127 are 0)
#pragma unroll
    for (int i = 0; i < 2; ++i)
#pragma unroll
        for (int j = 0; j < 4; ++j) {
            int r = row0 + wm * 32 + i * 16 + (lane >> 2);
            int col = wn * 32 + j * 8 + (lane & 3) * 2;
            if (r < NN)
                g_m2[r * 64 + (col >> 1)] =
                    __floats2bfloat162_rn(c[i][j][0], c[i][j][1]);
            if (r + 8 < NN)
                g_m2[(r + 8) * 64 + (col >> 1)] =
                    __floats2bfloat162_rn(c[i][j][2], c[i][j][3]);
        }
}

// ---------------- fused GRU (+ optional next-layer m GEMM) ----------------
// smem: Aa(32KB) + Ah(32KB) + RZ(32KB) = 96KB. r/z parked in smem (same-thread).
__global__ __launch_bounds__(256, 2) void k_gru(const unsigned* __restrict__ Bih,
                                                const unsigned* __restrict__ Bhh,
                                                const float* __restrict__ b_ih,
                                                const float* __restrict__ b_hh,
                                                const unsigned* __restrict__ Bm) {
    extern __shared__ unsigned smg[];
    unsigned* Aa = smg;            // agg, fragment-permuted
    unsigned* Ah = smg + 8192;     // h,   fragment-permuted
    unsigned* RZ = smg + 16384;    // r/z stash: [slot*256 + tid]
    int t = threadIdx.x, lane = t & 31, w = t >> 5;
    int wm = w >> 2, wn = w & 3;
    int row0 = blockIdx.x * 64;
    stageA64(Aa, g_agg, row0, t);
    stageA64(Ah, g_h, row0, t);
    __syncthreads();

    // r (g=0) and z (g=1): joint gi+gh accumulation, sigmoid, stash to smem
#pragma unroll
    for (int g = 0; g < 2; ++g) {
        float c[2][4][4];
        zeroC(c);
        mmaAcc(Aa, Bih + g * 16384, c, wm, wn, lane);
        mmaAcc(Ah, Bhh + g * 16384, c, wm, wn, lane);
#pragma unroll
        for (int i = 0; i < 2; ++i)
#pragma unroll
            for (int j = 0; j < 4; ++j) {
                int col = wn * 32 + j * 8 + (lane & 3) * 2;
                float b0 = b_ih[g * 128 + col] + b_hh[g * 128 + col];
                float b1 = b_ih[g * 128 + col + 1] + b_hh[g * 128 + col + 1];
#pragma unroll
                for (int half = 0; half < 2; ++half) {
                    float v0 = 1.f / (1.f + expf(-(c[i][j][half * 2 + 0] + b0)));
                    float v1 = 1.f / (1.f + expf(-(c[i][j][half * 2 + 1] + b1)));
                    __nv_bfloat162 p = __floats2bfloat162_rn(v0, v1);
                    RZ[(g * 16 + (i * 4 + j) * 2 + half) * 256 + t] = *(unsigned*)&p;
                }
            }
    }
    // n gate: dual accumulators, then GRU update, h in place (block owns rows)
    {
        float ci[2][4][4], ch[2][4][4];
        zeroC(ci);
        zeroC(ch);
        mmaAcc(Aa, Bih + 32768, ci, wm, wn, lane);
        mmaAcc(Ah, Bhh + 32768, ch, wm, wn, lane);
        if (Bm) __syncthreads();   // all warps done reading Aa before restage
#pragma unroll
        for (int i = 0; i < 2; ++i)
#pragma unroll
            for (int j = 0; j < 4; ++j) {
                int r0 = row0 + wm * 32 + i * 16 + (lane >> 2);
                int col = wn * 32 + j * 8 + (lane & 3) * 2;
                float bi0 = b_ih[256 + col], bi1 = b_ih[256 + col + 1];
                float bh0 = b_hh[256 + col], bh1 = b_hh[256 + col + 1];
#pragma unroll
                for (int half = 0; half < 2; ++half) {
                    int row = r0 + half * 8;
                    float2 o = make_float2(0.f, 0.f);
                    if (row < NN) {
                        unsigned rp = RZ[((i * 4 + j) * 2 + half) * 256 + t];
                        unsigned zp = RZ[(16 + (i * 4 + j) * 2 + half) * 256 + t];
                        float2 rr = __bfloat1622float2(*(__nv_bfloat162*)&rp);
                        float2 zz = __bfloat1622float2(*(__nv_bfloat162*)&zp);
                        float2 ho = *(const float2*)&g_h[row * 128 + col];
                        float n0 = tanhf(ci[i][j][half * 2 + 0] + bi0 +
                                         rr.x * (ch[i][j][half * 2 + 0] + bh0));
                        float n1 = tanhf(ci[i][j][half * 2 + 1] + bi1 +
                                         rr.y * (ch[i][j][half * 2 + 1] + bh1));
                        o = make_float2((1.f - zz.x) * n0 + zz.x * ho.x,
                                        (1.f - zz.y) * n1 + zz.y * ho.y);
                        *(float2*)&g_h[row * 128 + col] = o;
                    }
                    if (Bm) {   // restage h' into Aa for the next-layer m GEMM
                        int m = row - row0;   // 0..63
                        Aa[aslot(m, col)]     = f2tf(o.x);
                        Aa[aslot(m, col + 1)] = f2tf(o.y);
                    }
                }
            }
    }
    // optional fused m = h' @ W_next
    if (Bm) {
        __syncthreads();
        float c[2][4][4];
        zeroC(c);
        mmaAcc(Aa, Bm, c, wm, wn, lane);
#pragma unroll
        for (int i = 0; i < 2; ++i)
#pragma unroll
            for (int j = 0; j < 4; ++j) {
                int r = row0 + wm * 32 + i * 16 + (lane >> 2);
                int col = wn * 32 + j * 8 + (lane & 3) * 2;
                if (r < NN)
                    g_m2[r * 64 + (col >> 1)] =
                        __floats2bfloat162_rn(c[i][j][0], c[i][j][1]);
                if (r + 8 < NN)
                    g_m2[(r + 8) * 64 + (col >> 1)] =
                        __floats2bfloat162_rn(c[i][j][2], c[i][j][3]);
            }
    }
}

// ---------------- classifier + log_softmax ----------------
__global__ void k_cls(const float* __restrict__ lw, const float* __restrict__ lb,
                      float* __restrict__ out) {
    int gt = blockIdx.x * blockDim.x + threadIdx.x;
    int row = gt >> 5;
    int lane = gt & 31;
    if (row >= NN) return;
    const float* hrow = g_h + row * 128;
    float acc[CC];
#pragma unroll
    for (int c = 0; c < CC; ++c) acc[c] = 0.f;
#pragma unroll
    for (int kq = 0; kq < 4; ++kq) {
        int k = lane + kq * 32;
        float hv = hrow[k];
#pragma unroll
        for (int c = 0; c < CC; ++c) acc[c] += hv * lw[c * 128 + k];
    }
#pragma unroll
    for (int c = 0; c < CC; ++c) {
#pragma unroll
        for (int off = 16; off; off >>= 1)
            acc[c] += __shfl_xor_sync(0xffffffffu, acc[c], off);
        acc[c] += lb[c];
    }
    float mx = acc[0];
#pragma unroll
    for (int c = 1; c < CC; ++c) mx = fmaxf(mx, acc[c]);
    float se = 0.f;
#pragma unroll
    for (int c = 0; c < CC; ++c) se += expf(acc[c] - mx);
    float lse = mx + logf(se);
    if (lane < CC) out[row * CC + lane] = acc[lane] - lse;
}

// ---------------- launch ----------------
extern "C" void kernel_launch(void* const* d_in, const int* in_sizes, int n_in,
                              void* d_out, int out_size) {
    const float* x     = (const float*)d_in[0];
    const void*  ei    = d_in[1];
    const float* W     = (const float*)d_in[2];
    const float* w_ih  = (const float*)d_in[3];
    const float* w_hh  = (const float*)d_in[4];
    const float* b_ih  = (const float*)d_in[5];
    const float* b_hh  = (const float*)d_in[6];
    const float* lw    = (const float*)d_in[7];
    const float* lb    = (const float*)d_in[8];
    float* out = (float*)d_out;

    unsigned *p_Wtp, *p_Wihp, *p_Whhp;
    cudaGetSymbolAddress((void**)&p_Wtp,  g_Wtp);
    cudaGetSymbolAddress((void**)&p_Wihp, g_Wihp);
    cudaGetSymbolAddress((void**)&p_Whhp, g_Whhp);

    cudaFuncSetAttribute(k_gru, cudaFuncAttributeMaxDynamicSharedMemorySize, 98304);

    const int NSCAN = (NN + 255) / 256;   // 196
    const int GB = (NN + 63) / 64;        // 782

    // ---- fork: pad/prep/m0 chain on side stream (independent of CSR build) ----
    cudaEventRecord(s_fork, 0);
    cudaStreamWaitEvent(s_side, s_fork, 0);
    k_prep<<<256, 256, 0, s_side>>>(W, w_ih, w_hh);
    k_mma0<<<GB, 256, 0, s_side>>>(x, p_Wtp);          // layer-0 m, K=64 from x
    k_pad<<<(NN * HH + 255) / 256, 256, 0, s_side>>>(x);
    cudaEventRecord(s_join, s_side);

    // ---- main stream: CSR build chain ----
    k_detect<<<1, 32>>>(ei);
    k_zero_deg<<<NSCAN, 256>>>();
    k_convhist<<<(2 * EE + 255) / 256, 256>>>(ei);
    k_scan1<<<NSCAN, 256>>>();
    k_scan2<<<1, 256>>>(NSCAN);
    k_scan3<<<NSCAN, 256>>>();
    k_fill<<<(EE + 255) / 256, 256>>>();

    // ---- join ----
    cudaStreamWaitEvent(0, s_join, 0);

    for (int l = 0; l < LL; ++l) {
        k_gather<<<(NN * 32 + 255) / 256, 256>>>();
        const unsigned* Bm = (l + 1 < LL) ? (p_Wtp + (l + 1) * HH * HH) : nullptr;
        k_gru<<<GB, 256, 98304>>>(p_Wihp, p_Whhp, b_ih, b_hh, Bm);
    }
    k_cls<<<(NN * 32 + 255) / 256, 256>>>(lw, lb, out);
}

// round 16
// speedup vs baseline: 1.4982x; 1.4982x over previous
#include <cuda_runtime.h>
#include <cuda_bf16.h>
#include <math.h>

#define NN 50000
#define EE 800000
#define HH 128
#define FIN 64
#define CC 16
#define LL 3

// ---------------- scratch (static device globals; no allocation) ----------------
__device__ float g_h[NN * HH];            // hidden state  [N,128]
__device__ __nv_bfloat162 g_m2[NN * 64];  // messages, bf16 pairs [N,128]
__device__ float g_agg[NN * HH];          // aggregated    [N,128]
__device__ unsigned g_Wtp[LL * HH * HH];  // W^T per layer, tf32 fragment-permuted
__device__ unsigned g_Wihp[3 * HH * HH];  // w_ih tf32 fragment-permuted
__device__ unsigned g_Whhp[3 * HH * HH];  // w_hh tf32 fragment-permuted
__device__ int   g_edge[2 * EE];
__device__ int   g_deg[NN];
__device__ int   g_rowptr[NN + 1];
__device__ int   g_cursor[NN];
__device__ int   g_col[EE];
__device__ int   g_bsum[256];
__device__ int   g_boff[256];
__device__ int   g_is64;

// ---------------- edge dtype probe ----------------
__global__ void k_detect(const void* ei) {
    if (blockIdx.x == 0 && threadIdx.x == 0) {
        const long long* p64 = (const long long*)ei;
        int ok64 = 1;
        for (int i = 0; i < 64; ++i) {
            long long v = p64[i];
            if (v < 0 || v >= NN) { ok64 = 0; break; }
        }
        g_is64 = ok64;
    }
}

// convert + histogram fused (g_deg must be zeroed first)
__global__ void k_convhist(const void* ei) {
    int e = blockIdx.x * blockDim.x + threadIdx.x;
    if (e < 2 * EE) {
        int v;
        if (g_is64) v = (int)((const long long*)ei)[e];
        else        v = ((const int*)ei)[e];
        g_edge[e] = v;
        if (e >= EE) atomicAdd(&g_deg[v], 1);   // dst half
    }
}

// ---------------- init ----------------
__global__ void k_pad(const float* __restrict__ x) {
    int i = blockIdx.x * blockDim.x + threadIdx.x;
    if (i < NN * HH) {
        int n = i >> 7, k = i & 127;
        g_h[i] = (k < FIN) ? x[n * FIN + k] : 0.f;
    }
}

__device__ __forceinline__ unsigned f2tf(float x) {
    unsigned r;
    asm("cvt.rna.tf32.f32 %0, %1;" : "=r"(r) : "f"(x));
    return r;
}

// Fragment-permuted B layout for mma.m16n8k8 tf32 B operand (full K=128)
__device__ __forceinline__ int bperm_off(int n, int k) {
    int g = n >> 7, nf = (n >> 3) & 15, nl = n & 7;
    int ks = k >> 3, hi = (k & 7) >> 2, c = k & 3;
    return ((g * 16 + nf) * 16 + ks) * 64 + (nl * 4 + c) * 2 + hi;
}

// pre-round + pre-permute all GEMM B operands once
__global__ void k_prep(const float* __restrict__ W,
                       const float* __restrict__ w_ih,
                       const float* __restrict__ w_hh) {
    int i = blockIdx.x * blockDim.x + threadIdx.x;   // 65536 threads
    if (i < LL * HH * HH) {
        int l = i >> 14;
        int rem = i & 16383;
        int n = rem >> 7, k = rem & 127;             // Bt[n][k] = W[l][k][n]
        g_Wtp[(l << 14) + bperm_off(n, k)] = f2tf(W[(l << 14) + k * 128 + n]);
    }
    if (i < 3 * HH * HH) {
        int n = i >> 7, k = i & 127;
        int off = bperm_off(n, k);
        g_Wihp[off] = f2tf(w_ih[i]);
        g_Whhp[off] = f2tf(w_hh[i]);
    }
}

// ---------------- CSR build ----------------
__global__ void k_zero_deg() {
    int i = blockIdx.x * blockDim.x + threadIdx.x;
    if (i < NN) g_deg[i] = 0;
}

__global__ void k_scan1() {
    __shared__ int s[256];
    int t = threadIdx.x;
    int idx = blockIdx.x * 256 + t;
    int v = (idx < NN) ? g_deg[idx] : 0;
    s[t] = v;
    __syncthreads();
#pragma unroll
    for (int off = 1; off < 256; off <<= 1) {
        int add = (t >= off) ? s[t - off] : 0;
        __syncthreads();
        s[t] += add;
        __syncthreads();
    }
    if (idx < NN) g_rowptr[idx] = s[t] - v;
    if (t == 255) g_bsum[blockIdx.x] = s[255];
}

__global__ void k_scan2(int nblocks) {
    __shared__ int s[256];
    int t = threadIdx.x;
    int v = (t < nblocks) ? g_bsum[t] : 0;
    s[t] = v;
    __syncthreads();
#pragma unroll
    for (int off = 1; off < 256; off <<= 1) {
        int add = (t >= off) ? s[t - off] : 0;
        __syncthreads();
        s[t] += add;
        __syncthreads();
    }
    if (t < nblocks) g_boff[t] = s[t] - v;
}

__global__ void k_scan3() {
    int idx = blockIdx.x * 256 + threadIdx.x;
    if (idx < NN) {
        int v = g_rowptr[idx] + g_boff[blockIdx.x];
        g_rowptr[idx] = v;
        g_cursor[idx] = v;
    }
    if (idx == 0) g_rowptr[NN] = EE;
}

__global__ void k_fill() {
    int e = blockIdx.x * blockDim.x + threadIdx.x;
    if (e < EE) {
        int d = g_edge[EE + e];
        int srcn = g_edge[e];
        int pos = atomicAdd(&g_cursor[d], 1);
        g_col[pos] = srcn;
    }
}

// ---------------- aggregation: warp per node, bf16 m rows ----------------
__global__ void k_gather() {
    int warp = (blockIdx.x * blockDim.x + threadIdx.x) >> 5;
    int lane = threadIdx.x & 31;
    if (warp >= NN) return;
    int beg = g_rowptr[warp], end = g_rowptr[warp + 1];
    float a0 = 0.f, a1 = 0.f, a2 = 0.f, a3 = 0.f;
    int e = beg;
    for (; e + 2 <= end; e += 2) {
        int s0 = g_col[e], s1 = g_col[e + 1];
        uint2 v0 = *(const uint2*)&g_m2[s0 * 64 + lane * 2];
        uint2 v1 = *(const uint2*)&g_m2[s1 * 64 + lane * 2];
        float2 p0 = __bfloat1622float2(*(__nv_bfloat162*)&v0.x);
        float2 p1 = __bfloat1622float2(*(__nv_bfloat162*)&v0.y);
        float2 q0 = __bfloat1622float2(*(__nv_bfloat162*)&v1.x);
        float2 q1 = __bfloat1622float2(*(__nv_bfloat162*)&v1.y);
        a0 += p0.x + q0.x;
        a1 += p0.y + q0.y;
        a2 += p1.x + q1.x;
        a3 += p1.y + q1.y;
    }
    if (e < end) {
        uint2 v0 = *(const uint2*)&g_m2[g_col[e] * 64 + lane * 2];
        float2 p0 = __bfloat1622float2(*(__nv_bfloat162*)&v0.x);
        float2 p1 = __bfloat1622float2(*(__nv_bfloat162*)&v0.y);
        a0 += p0.x; a1 += p0.y; a2 += p1.x; a3 += p1.y;
    }
    *(float4*)&g_agg[warp * HH + lane * 4] = make_float4(a0, a1, a2, a3);
}

// ---------------- shared GEMM machinery (M-tile 64, full K=128) ----------------
__device__ __forceinline__ void stageA64(unsigned* As, const float* __restrict__ A,
                                         int row0, int t) {
#pragma unroll
    for (int q = 0; q < 8; ++q) {
        int idx = q * 256 + t;
        int m = idx >> 5, kq = idx & 31;
        int row = row0 + m;
        float4 v = make_float4(0.f, 0.f, 0.f, 0.f);
        if (row < NN) v = *(const float4*)&A[row * 128 + kq * 4];
        int mf = m >> 4, r16 = m & 15;
        int lb = (r16 & 7) * 4, rh = r16 >> 3;
        int ks = kq >> 1, hi = kq & 1, reg = hi * 2 + rh;
        unsigned* dst = &As[(mf * 16 + ks) * 128];
        dst[(lb + 0) * 4 + reg] = f2tf(v.x);
        dst[(lb + 1) * 4 + reg] = f2tf(v.y);
        dst[(lb + 2) * 4 + reg] = f2tf(v.z);
        dst[(lb + 3) * 4 + reg] = f2tf(v.w);
    }
}

// staged A-slot for a single (m, k) element
__device__ __forceinline__ int aslot(int m, int k) {
    return ((m >> 4) * 16 + (k >> 3)) * 128 + ((m & 7) * 4 + (k & 3)) * 4 +
           ((k >> 2) & 1) * 2 + ((m >> 3) & 1);
}

// accumulate one 64x128xK group GEMM into c (no zero-init); KS = k-steps
template <int KS>
__device__ __forceinline__ void mmaAccT(const unsigned* As, const unsigned* __restrict__ Bg,
                                        float c[2][4][4], int wm, int wn, int lane) {
#pragma unroll
    for (int ks = 0; ks < KS; ++ks) {
        uint2 b[4];
#pragma unroll
        for (int j = 0; j < 4; ++j)
            b[j] = *(const uint2*)&Bg[((wn * 4 + j) * 16 + ks) * 64 + lane * 2];
        uint4 a[2];
#pragma unroll
        for (int i = 0; i < 2; ++i)
            a[i] = *(const uint4*)&As[((wm * 2 + i) * 16 + ks) * 128 + lane * 4];
#pragma unroll
        for (int i = 0; i < 2; ++i)
#pragma unroll
            for (int j = 0; j < 4; ++j) {
                asm volatile(
                    "mma.sync.aligned.m16n8k8.row.col.f32.tf32.tf32.f32 "
                    "{%0,%1,%2,%3}, {%4,%5,%6,%7}, {%8,%9}, {%0,%1,%2,%3};"
                    : "+f"(c[i][j][0]), "+f"(c[i][j][1]),
                      "+f"(c[i][j][2]), "+f"(c[i][j][3])
                    : "r"(a[i].x), "r"(a[i].y), "r"(a[i].z), "r"(a[i].w),
                      "r"(b[j].x), "r"(b[j].y));
            }
    }
}
#define mmaAcc mmaAccT<16>

__device__ __forceinline__ void zeroC(float c[2][4][4]) {
#pragma unroll
    for (int i = 0; i < 2; ++i)
#pragma unroll
        for (int j = 0; j < 4; ++j)
#pragma unroll
            for (int r = 0; r < 4; ++r) c[i][j][r] = 0.f;
}

// ---------------- layer-0 m GEMM: reads x directly, K=64 ----------------
__global__ __launch_bounds__(256, 2) void k_mma0(const float* __restrict__ x,
                                                 const unsigned* __restrict__ Bp) {
    __shared__ unsigned As[8192];
    int t = threadIdx.x, lane = t & 31, w = t >> 5;
    int wm = w >> 2, wn = w & 3;
    int row0 = blockIdx.x * 64;
    // stage x tile: 64 rows x 64 cols (k-steps 0..7 of the fragment layout)
#pragma unroll
    for (int q = 0; q < 4; ++q) {
        int idx = q * 256 + t;
        int m = idx >> 4, kq = idx & 15;        // kq: quad of 4 within 64 cols
        int row = row0 + m;
        float4 v = make_float4(0.f, 0.f, 0.f, 0.f);
        if (row < NN) v = *(const float4*)&x[row * FIN + kq * 4];
        int mf = m >> 4, r16 = m & 15;
        int lb = (r16 & 7) * 4, rh = r16 >> 3;
        int ks = kq >> 1, hi = kq & 1, reg = hi * 2 + rh;
        unsigned* dst = &As[(mf * 16 + ks) * 128];
        dst[(lb + 0) * 4 + reg] = f2tf(v.x);
        dst[(lb + 1) * 4 + reg] = f2tf(v.y);
        dst[(lb + 2) * 4 + reg] = f2tf(v.z);
        dst[(lb + 3) * 4 + reg] = f2tf(v.w);
    }
    __syncthreads();
    float c[2][4][4];
    zeroC(c);
    mmaAccT<8>(As, Bp, c, wm, wn, lane);       // only K=64 (h cols 64..127 are 0)
#pragma unroll
    for (int i = 0; i < 2; ++i)
#pragma unroll
        for (int j = 0; j < 4; ++j) {
            int r = row0 + wm * 32 + i * 16 + (lane >> 2);
            int col = wn * 32 + j * 8 + (lane & 3) * 2;
            if (r < NN)
                g_m2[r * 64 + (col >> 1)] =
                    __floats2bfloat162_rn(c[i][j][0], c[i][j][1]);
            if (r + 8 < NN)
                g_m2[(r + 8) * 64 + (col >> 1)] =
                    __floats2bfloat162_rn(c[i][j][2], c[i][j][3]);
        }
}

// ---------------- fused GRU (+ optional next-layer m GEMM) ----------------
// smem: Aa(32KB) + Ah(32KB) + RZ(32KB) = 96KB. r/z parked in smem (same-thread).
__global__ __launch_bounds__(256, 2) void k_gru(const unsigned* __restrict__ Bih,
                                                const unsigned* __restrict__ Bhh,
                                                const float* __restrict__ b_ih,
                                                const float* __restrict__ b_hh,
                                                const unsigned* __restrict__ Bm) {
    extern __shared__ unsigned smg[];
    unsigned* Aa = smg;            // agg, fragment-permuted
    unsigned* Ah = smg + 8192;     // h,   fragment-permuted
    unsigned* RZ = smg + 16384;    // r/z stash: [slot*256 + tid]
    int t = threadIdx.x, lane = t & 31, w = t >> 5;
    int wm = w >> 2, wn = w & 3;
    int row0 = blockIdx.x * 64;
    stageA64(Aa, g_agg, row0, t);
    stageA64(Ah, g_h, row0, t);
    __syncthreads();

    // r (g=0) and z (g=1): joint gi+gh accumulation, sigmoid, stash to smem
#pragma unroll
    for (int g = 0; g < 2; ++g) {
        float c[2][4][4];
        zeroC(c);
        mmaAcc(Aa, Bih + g * 16384, c, wm, wn, lane);
        mmaAcc(Ah, Bhh + g * 16384, c, wm, wn, lane);
#pragma unroll
        for (int i = 0; i < 2; ++i)
#pragma unroll
            for (int j = 0; j < 4; ++j) {
                int col = wn * 32 + j * 8 + (lane & 3) * 2;
                float b0 = b_ih[g * 128 + col] + b_hh[g * 128 + col];
                float b1 = b_ih[g * 128 + col + 1] + b_hh[g * 128 + col + 1];
#pragma unroll
                for (int half = 0; half < 2; ++half) {
                    float v0 = 1.f / (1.f + expf(-(c[i][j][half * 2 + 0] + b0)));
                    float v1 = 1.f / (1.f + expf(-(c[i][j][half * 2 + 1] + b1)));
                    __nv_bfloat162 p = __floats2bfloat162_rn(v0, v1);
                    RZ[(g * 16 + (i * 4 + j) * 2 + half) * 256 + t] = *(unsigned*)&p;
                }
            }
    }
    // n gate: dual accumulators, then GRU update, h in place (block owns rows)
    {
        float ci[2][4][4], ch[2][4][4];
        zeroC(ci);
        zeroC(ch);
        mmaAcc(Aa, Bih + 32768, ci, wm, wn, lane);
        mmaAcc(Ah, Bhh + 32768, ch, wm, wn, lane);
        if (Bm) __syncthreads();   // all warps done reading Aa before restage
#pragma unroll
        for (int i = 0; i < 2; ++i)
#pragma unroll
            for (int j = 0; j < 4; ++j) {
                int r0 = row0 + wm * 32 + i * 16 + (lane >> 2);
                int col = wn * 32 + j * 8 + (lane & 3) * 2;
                float bi0 = b_ih[256 + col], bi1 = b_ih[256 + col + 1];
                float bh0 = b_hh[256 + col], bh1 = b_hh[256 + col + 1];
#pragma unroll
                for (int half = 0; half < 2; ++half) {
                    int row = r0 + half * 8;
                    float2 o = make_float2(0.f, 0.f);
                    if (row < NN) {
                        unsigned rp = RZ[((i * 4 + j) * 2 + half) * 256 + t];
                        unsigned zp = RZ[(16 + (i * 4 + j) * 2 + half) * 256 + t];
                        float2 rr = __bfloat1622float2(*(__nv_bfloat162*)&rp);
                        float2 zz = __bfloat1622float2(*(__nv_bfloat162*)&zp);
                        float2 ho = *(const float2*)&g_h[row * 128 + col];
                        float n0 = tanhf(ci[i][j][half * 2 + 0] + bi0 +
                                         rr.x * (ch[i][j][half * 2 + 0] + bh0));
                        float n1 = tanhf(ci[i][j][half * 2 + 1] + bi1 +
                                         rr.y * (ch[i][j][half * 2 + 1] + bh1));
                        o = make_float2((1.f - zz.x) * n0 + zz.x * ho.x,
                                        (1.f - zz.y) * n1 + zz.y * ho.y);
                        *(float2*)&g_h[row * 128 + col] = o;
                    }
                    if (Bm) {   // restage h' into Aa for the next-layer m GEMM
                        int m = row - row0;   // 0..63
                        Aa[aslot(m, col)]     = f2tf(o.x);
                        Aa[aslot(m, col + 1)] = f2tf(o.y);
                    }
                }
            }
    }
    // optional fused m = h' @ W_next
    if (Bm) {
        __syncthreads();
        float c[2][4][4];
        zeroC(c);
        mmaAcc(Aa, Bm, c, wm, wn, lane);
#pragma unroll
        for (int i = 0; i < 2; ++i)
#pragma unroll
            for (int j = 0; j < 4; ++j) {
                int r = row0 + wm * 32 + i * 16 + (lane >> 2);
                int col = wn * 32 + j * 8 + (lane & 3) * 2;
                if (r < NN)
                    g_m2[r * 64 + (col >> 1)] =
                        __floats2bfloat162_rn(c[i][j][0], c[i][j][1]);
                if (r + 8 < NN)
                    g_m2[(r + 8) * 64 + (col >> 1)] =
                        __floats2bfloat162_rn(c[i][j][2], c[i][j][3]);
            }
    }
}

// ---------------- classifier + log_softmax ----------------
__global__ void k_cls(const float* __restrict__ lw, const float* __restrict__ lb,
                      float* __restrict__ out) {
    int gt = blockIdx.x * blockDim.x + threadIdx.x;
    int row = gt >> 5;
    int lane = gt & 31;
    if (row >= NN) return;
    const float* hrow = g_h + row * 128;
    float acc[CC];
#pragma unroll
    for (int c = 0; c < CC; ++c) acc[c] = 0.f;
#pragma unroll
    for (int kq = 0; kq < 4; ++kq) {
        int k = lane + kq * 32;
        float hv = hrow[k];
#pragma unroll
        for (int c = 0; c < CC; ++c) acc[c] += hv * lw[c * 128 + k];
    }
#pragma unroll
    for (int c = 0; c < CC; ++c) {
#pragma unroll
        for (int off = 16; off; off >>= 1)
            acc[c] += __shfl_xor_sync(0xffffffffu, acc[c], off);
        acc[c] += lb[c];
    }
    float mx = acc[0];
#pragma unroll
    for (int c = 1; c < CC; ++c) mx = fmaxf(mx, acc[c]);
    float se = 0.f;
#pragma unroll
    for (int c = 0; c < CC; ++c) se += expf(acc[c] - mx);
    float lse = mx + logf(se);
    if (lane < CC) out[row * CC + lane] = acc[lane] - lse;
}

// ---------------- launch ----------------
extern "C" void kernel_launch(void* const* d_in, const int* in_sizes, int n_in,
                              void* d_out, int out_size) {
    const float* x     = (const float*)d_in[0];
    const void*  ei    = d_in[1];
    const float* W     = (const float*)d_in[2];
    const float* w_ih  = (const float*)d_in[3];
    const float* w_hh  = (const float*)d_in[4];
    const float* b_ih  = (const float*)d_in[5];
    const float* b_hh  = (const float*)d_in[6];
    const float* lw    = (const float*)d_in[7];
    const float* lb    = (const float*)d_in[8];
    float* out = (float*)d_out;

    unsigned *p_Wtp, *p_Wihp, *p_Whhp;
    cudaGetSymbolAddress((void**)&p_Wtp,  g_Wtp);
    cudaGetSymbolAddress((void**)&p_Wihp, g_Wihp);
    cudaGetSymbolAddress((void**)&p_Whhp, g_Whhp);

    cudaFuncSetAttribute(k_gru, cudaFuncAttributeMaxDynamicSharedMemorySize, 98304);

    const int NSCAN = (NN + 255) / 256;   // 196
    const int GB = (NN + 63) / 64;        // 782

    // single stream (stream fork inside this harness's capture regresses; R15)
    k_detect<<<1, 32>>>(ei);
    k_zero_deg<<<NSCAN, 256>>>();
    k_convhist<<<(2 * EE + 255) / 256, 256>>>(ei);
    // independent prep chain slotted here: overlaps convhist's wave tail,
    // and scan1 depends only on g_deg (done by convhist).
    k_prep<<<256, 256>>>(W, w_ih, w_hh);
    k_mma0<<<GB, 256>>>(x, p_Wtp);        // layer-0 m, K=64 straight from x
    k_pad<<<(NN * HH + 255) / 256, 256>>>(x);
    k_scan1<<<NSCAN, 256>>>();
    k_scan2<<<1, 256>>>(NSCAN);
    k_scan3<<<NSCAN, 256>>>();
    k_fill<<<(EE + 255) / 256, 256>>>();

    for (int l = 0; l < LL; ++l) {
        k_gather<<<(NN * 32 + 255) / 256, 256>>>();
        const unsigned* Bm = (l + 1 < LL) ? (p_Wtp + (l + 1) * HH * HH) : nullptr;
        k_gru<<<GB, 256, 98304>>>(p_Wihp, p_Whhp, b_ih, b_hh, Bm);
    }
    k_cls<<<(NN * 32 + 255) / 256, 256>>>(lw, lb, out);
}